// round 1
// baseline (speedup 1.0000x reference)
#include <cuda_runtime.h>
#include <math.h>

// Problem constants (fixed by the reference: H=1024, B=64, T=1024)
#define BB 64
#define TS 1024
#define HS 1024
#define TT 32            // t-tile per CTA
#define NT (TS / TT)     // 32 tiles per batch row
#define PITCH 1025       // stile row pitch (odd -> conflict-free strided stores)
#define RP 33            // reduction scratch pitch

// Deterministic partial buffer: [B][NT][H] fp32 = 8 MB
__device__ float g_partial[BB * NT * HS];

// Dynamic smem layout (floats):
//   sdh   [HS]                 : decoder_hidden row for this b
//   stile [TT * PITCH]         : tile, indexed stile[t*PITCH + h]
//   sredS/ sredMax / sredMin [32*RP] : cross-warp stat exchange
//   sInv  [TT]                 : 1/denom per t
#define SMEM_FLOATS (HS + TT * PITCH + 3 * 32 * RP + TT)

__global__ void __launch_bounds__(1024, 1)
attn_tile_kernel(const float* __restrict__ dh, const float* __restrict__ enc) {
    extern __shared__ float smem[];
    float* sdh     = smem;
    float* stile   = sdh + HS;
    float* sredS   = stile + TT * PITCH;
    float* sredMax = sredS + 32 * RP;
    float* sredMin = sredMax + 32 * RP;
    float* sInv    = sredMin + 32 * RP;

    const int tid  = threadIdx.x;
    const int w    = tid >> 5;        // warp 0..31
    const int l    = tid & 31;        // lane
    const int b    = blockIdx.x >> 5; // NT == 32
    const int tile = blockIdx.x & (NT - 1);
    const int t0   = tile * TT;

    // decoder_hidden row -> smem
    sdh[tid] = dh[b * HS + tid];
    __syncthreads();

    // ---- Pass 1: stream-load tile, fused score-dot + max/min per t ----
    // warp w handles h in [w*32, w*32+32); lane l handles t = t0 + l.
    // Global access per iter: 32 consecutive floats at fixed h -> 1 cacheline/warp.
    const float* gbase = enc + (size_t)b * TS + t0 + l;
    float sp   = 0.0f;
    float vmax = -INFINITY;
    float vmin =  INFINITY;
    const int hbase = w * 32;
    #pragma unroll
    for (int k = 0; k < 32; ++k) {
        const int h = hbase + k;
        const float v = __ldg(gbase + (size_t)h * (BB * TS));
        stile[l * PITCH + h] = v;        // stride 1025 between lanes: conflict-free
        sp   = fmaf(v, sdh[h], sp);
        vmax = fmaxf(vmax, v);
        vmin = fminf(vmin, v);
    }
    sredS[w * RP + l]   = sp;
    sredMax[w * RP + l] = vmax;
    sredMin[w * RP + l] = vmin;
    __syncthreads();

    // ---- Pass 2: warp w owns t = w. Combine stats across warps, exp + denom ----
    {
        float s  = sredS[l * RP + w];    // stride RP=33: conflict-free
        float mx = sredMax[l * RP + w];
        float mn = sredMin[l * RP + w];
        #pragma unroll
        for (int off = 16; off; off >>= 1) {
            s  += __shfl_xor_sync(0xffffffffu, s, off);
            mx  = fmaxf(mx, __shfl_xor_sync(0xffffffffu, mx, off));
            mn  = fminf(mn, __shfl_xor_sync(0xffffffffu, mn, off));
        }
        // max over h of (v * s):
        const float M = (s >= 0.0f) ? mx * s : mn * s;

        float dsum = 0.0f;
        #pragma unroll
        for (int k = 0; k < 32; ++k) {
            const int h = l + 32 * k;    // consecutive lanes -> consecutive banks
            const float v = stile[w * PITCH + h];
            const float e = __expf(fmaf(v, s, -M));   // e in (0,1], exact max used
            stile[w * PITCH + h] = e;    // store exp once; reused in pass 3
            dsum += e;
        }
        #pragma unroll
        for (int off = 16; off; off >>= 1)
            dsum += __shfl_xor_sync(0xffffffffu, dsum, off);
        if (l == 0) sInv[w] = 1.0f / dsum;
    }
    __syncthreads();

    // ---- Pass 3: per-h accumulation over the 32 t's of this tile ----
    float acc = 0.0f;
    #pragma unroll
    for (int t = 0; t < TT; ++t)
        acc = fmaf(stile[t * PITCH + tid], sInv[t], acc);

    g_partial[(size_t)blockIdx.x * HS + tid] = acc;
}

// Final reduce: out[b,h] = sum over NT tiles of partials. Deterministic order.
__global__ void __launch_bounds__(1024)
attn_reduce_kernel(float* __restrict__ out) {
    const int b = blockIdx.x;
    const int h = threadIdx.x;
    float acc = 0.0f;
    #pragma unroll
    for (int t = 0; t < NT; ++t)
        acc += g_partial[((size_t)(b * NT + t)) * HS + h];
    out[b * HS + h] = acc;
}

extern "C" void kernel_launch(void* const* d_in, const int* in_sizes, int n_in,
                              void* d_out, int out_size) {
    // Identify inputs by size: decoder_hidden = B*H, encoder_outputs = H*B*T.
    const float* dh  = (const float*)d_in[0];
    const float* enc = (const float*)d_in[1];
    if (n_in >= 2 && in_sizes[0] > in_sizes[1]) {
        enc = (const float*)d_in[0];
        dh  = (const float*)d_in[1];
    }
    float* out = (float*)d_out;

    static_assert(SMEM_FLOATS * sizeof(float) < 227 * 1024, "smem budget");
    cudaFuncSetAttribute(attn_tile_kernel,
                         cudaFuncAttributeMaxDynamicSharedMemorySize,
                         SMEM_FLOATS * (int)sizeof(float));

    attn_tile_kernel<<<BB * NT, 1024, SMEM_FLOATS * sizeof(float)>>>(dh, enc);
    attn_reduce_kernel<<<BB, 1024>>>(out);
}

// round 2
// speedup vs baseline: 1.3293x; 1.3293x over previous
#include <cuda_runtime.h>
#include <math.h>

// Fixed problem shape: H=1024, B=64, T=1024
#define BB 64
#define TS 1024
#define HS 1024
#define TT 16                    // t per subtile
#define SUBS 2                   // subtiles per CTA
#define PAIRS (TS / (TT * SUBS)) // 32 CTA-columns per batch row
#define THREADS 512
#define RP 17                    // stat-buffer pitch (odd -> conflict-free)

// Deterministic per-CTA partials: [B][PAIRS][H] = 8 MB
__device__ float g_partial[BB * PAIRS * HS];

// In-register 16x16 transpose-reduce over a half-warp.
// a[0..15] holds 16 column-values per lane; after call a[0] = sum over the 16
// half-warp lanes of column hw (hw = lane & 15).
__device__ __forceinline__ void tr_reduce16(float* a, int hw) {
    #pragma unroll
    for (int s = 8; s >= 1; s >>= 1) {
        const bool up = (hw & s) != 0;
        #pragma unroll
        for (int i = 0; i < s; ++i) {
            const float give = up ? a[i] : a[i + s];
            const float keep = up ? a[i + s] : a[i];
            const float got  = __shfl_xor_sync(0xffffffffu, give, s);
            a[i] = keep + got;
        }
    }
}

__global__ void __launch_bounds__(THREADS, 2)
attn_main(const float* __restrict__ dh, const float* __restrict__ enc) {
    __shared__ float sdh[HS];
    __shared__ float srA[32 * RP];
    __shared__ float srB[32 * RP];
    __shared__ float srC[32 * RP];
    __shared__ float sS[TT], sM[TT], sInv[TT];

    const int tid = threadIdx.x;
    const int w   = tid >> 5;            // warp 0..15
    const int l   = tid & 31;
    const int tt  = l & 15;              // t within subtile
    const int hh  = l >> 4;              // h half within warp
    const int b    = blockIdx.x >> 5;
    const int pair = blockIdx.x & 31;
    const int hbase = w * 64 + hh * 32;  // 32 h's per thread at hbase+k
    const int c     = (w << 1) | hh;     // h-chunk id 0..31

    sdh[tid]           = dh[b * HS + tid];
    sdh[tid + THREADS] = dh[b * HS + tid + THREADS];
    __syncthreads();

    float acc0 = 0.0f, acc1 = 0.0f;
    const size_t hstride = (size_t)BB * TS;

    #pragma unroll
    for (int sub = 0; sub < SUBS; ++sub) {
        const int t0 = pair * (TT * SUBS) + sub * TT;
        const float* gp = enc + (size_t)hbase * hstride + (size_t)b * TS + t0 + tt;

        // ---- load tile into registers, fused dot + max/min partials ----
        float v[32];
        float sp = 0.0f, vmx = -INFINITY, vmn = INFINITY;
        #pragma unroll
        for (int k = 0; k < 32; ++k) {
            v[k] = __ldg(gp + (size_t)k * hstride);
            sp   = fmaf(v[k], sdh[hbase + k], sp);
            vmx  = fmaxf(vmx, v[k]);
            vmn  = fminf(vmn, v[k]);
        }
        srA[c * RP + tt] = sp;
        srB[c * RP + tt] = vmx;
        srC[c * RP + tt] = vmn;
        __syncthreads();

        // ---- warp w owns t = tt0 + w: combine 32 h-chunk partials ----
        {
            float s  = srA[l * RP + w];
            float mx = srB[l * RP + w];
            float mn = srC[l * RP + w];
            #pragma unroll
            for (int off = 16; off; off >>= 1) {
                s  += __shfl_xor_sync(0xffffffffu, s, off);
                mx  = fmaxf(mx, __shfl_xor_sync(0xffffffffu, mx, off));
                mn  = fminf(mn, __shfl_xor_sync(0xffffffffu, mn, off));
            }
            if (l == 0) {
                sS[w] = s;
                sM[w] = (s >= 0.0f) ? mx * s : mn * s;  // max_h (v*s)
            }
        }
        __syncthreads();

        // ---- exp on registers + denominator partial ----
        const float st = sS[tt];
        const float Mt = sM[tt];
        float dsum = 0.0f;
        #pragma unroll
        for (int k = 0; k < 32; ++k) {
            v[k] = __expf(fmaf(v[k], st, -Mt));
            dsum += v[k];
        }
        srA[c * RP + tt] = dsum;
        __syncthreads();

        {
            float d = srA[l * RP + w];
            #pragma unroll
            for (int off = 16; off; off >>= 1)
                d += __shfl_xor_sync(0xffffffffu, d, off);
            if (l == 0) sInv[w] = 1.0f / d;
        }
        __syncthreads();

        // ---- scale + in-register transpose-reduce over the 16 t's ----
        const float rinv = sInv[tt];
        #pragma unroll
        for (int k = 0; k < 32; ++k) v[k] *= rinv;

        tr_reduce16(v, tt);        // group A: columns hbase + 0..15
        tr_reduce16(v + 16, tt);   // group B: columns hbase + 16..31
        acc0 += v[0];              // sum over t for h = hbase + tt
        acc1 += v[16];             // sum over t for h = hbase + 16 + tt
    }

    const int h0 = hbase + tt;
    float* pr = g_partial + ((size_t)b * PAIRS + pair) * HS;
    pr[h0]      = acc0;
    pr[h0 + 16] = acc1;
}

// out[b,h] = sum over PAIRS partials (deterministic order)
__global__ void __launch_bounds__(256)
attn_reduce(float* __restrict__ out) {
    const int b = blockIdx.x >> 2;
    const int h = ((blockIdx.x & 3) << 8) + threadIdx.x;
    float acc = 0.0f;
    #pragma unroll
    for (int p = 0; p < PAIRS; ++p)
        acc += g_partial[((size_t)b * PAIRS + p) * HS + h];
    out[b * HS + h] = acc;
}

extern "C" void kernel_launch(void* const* d_in, const int* in_sizes, int n_in,
                              void* d_out, int out_size) {
    const float* dh  = (const float*)d_in[0];
    const float* enc = (const float*)d_in[1];
    if (n_in >= 2 && in_sizes[0] > in_sizes[1]) {
        enc = (const float*)d_in[0];
        dh  = (const float*)d_in[1];
    }
    float* out = (float*)d_out;

    attn_main<<<BB * PAIRS, THREADS>>>(dh, enc);
    attn_reduce<<<BB * 4, 256>>>(out);
}